// round 2
// baseline (speedup 1.0000x reference)
#include <cuda_runtime.h>
#include <math.h>

#define NEGF   (-1e30f)
#define MAXB   16
#define NCH    32            // chunks for denominator scan
#define RING   256
#define RM     (RING - 1)
#define LOG2E_F 1.4426950408889634f
#define LN2_F   0.6931471805599453f

// Scratch (static device arrays; no allocations allowed)
__device__ float g_num[MAXB];                       // numerator logZ per batch (natural log)
__device__ float g_LP[MAXB * NCH * 8 * 8];          // [b][c][j][i] log chunk matrices

// ---------------- helpers ----------------
__device__ __forceinline__ float ex2f_(float x) {
    float r; asm("ex2.approx.ftz.f32 %0, %1;" : "=f"(r) : "f"(x)); return r;
}
__device__ __forceinline__ float lg2f_(float x) {
    float r; asm("lg2.approx.ftz.f32 %0, %1;" : "=f"(r) : "f"(x)); return r;
}
// logaddexp in log2 domain: returns log2(2^a + 2^b)
__device__ __forceinline__ float lae2(float a, float b) {
    float m = fmaxf(a, b);
    float d = fminf(a, b) - m;            // <= 0
    return m + lg2f_(1.0f + ex2f_(d));
}
__device__ __forceinline__ unsigned ld_acq_shared(const unsigned* p) {
    unsigned v;
    unsigned a = (unsigned)__cvta_generic_to_shared(p);
    asm volatile("ld.acquire.cta.shared.u32 %0, [%1];" : "=r"(v) : "r"(a));
    return v;
}
__device__ __forceinline__ void st_rel_shared(unsigned* p, unsigned v) {
    unsigned a = (unsigned)__cvta_generic_to_shared(p);
    asm volatile("st.release.cta.shared.u32 [%0], %1;" :: "r"(a), "r"(v));
}

// One numerator step (log2 domain). PE0/PX0: lane-0 boundary inputs.
#define NUM_STEP(T_, EME, EMX, PE0, PX0) do {                                 \
    float pe = __shfl_up_sync(0xffffffffu, a_e, 1);                           \
    float px = __shfl_up_sync(0xffffffffu, a_x, 1);                           \
    if (lane == 0) { pe = (PE0); px = (PX0); }                                \
    float ne_ = (EME) + lae2(pe + t_ee, px + t_xe);                           \
    float nx_ = (EMX) + lae2(a_e + t_ex, a_x + t_xx);                         \
    int tp_ = (T_) + 4; tp_ = (tp_ > len - 1) ? (len - 1) : tp_;              \
    (EME) = __ldg(emb + tp_ * 8 + es) * LOG2E_F;                              \
    (EMX) = __ldg(emb + tp_ * 8 + xs) * LOG2E_F;                              \
    a_e = ne_; a_x = nx_;                                                     \
    if (lane == 31) {                                                         \
        ring_e[warp][(T_) & RM] = a_e;                                        \
        ring_x[warp][(T_) & RM] = a_x;                                        \
        st_rel_shared(&cnt[warp], (unsigned)(T_));                            \
    }                                                                         \
} while (0)

extern "C" __global__ void __launch_bounds__(256, 1)
ctccrf_main(const float* __restrict__ em,      // (B,T,8)
            const float* __restrict__ trans,   // (8,8)
            const float* __restrict__ bos,     // (8)
            const float* __restrict__ eos,     // (8)
            const int*   __restrict__ lengths, // (B)
            const int*   __restrict__ targets, // (B,L)
            const int*   __restrict__ tlens,   // (B)
            int B, int T, int L)
{
    if ((int)blockIdx.x < B) {
        // ------- Numerator: one CTA per batch, lane u = thread, warp-skewed pipeline -------
        const int b    = blockIdx.x;
        const int u    = threadIdx.x;          // 0..L-1 (L == 256)
        const int lane = u & 31;
        const int warp = u >> 5;

        __shared__ float ring_e[8][RING];
        __shared__ float ring_x[8][RING];
        __shared__ unsigned cnt[8];

        const int len = lengths[b];
        const int tg  = __ldg(targets + b * L + u);
        const int es  = tg;
        const int xs  = tg + 4;
        const int tgp = (u == 0) ? tg : __ldg(targets + b * L + u - 1);
        // constants in log2 domain
        const float t_ee = __ldg(trans + tgp * 8 + es) * LOG2E_F;
        const float t_xe = __ldg(trans + (tgp + 4) * 8 + es) * LOG2E_F;
        const float t_ex = __ldg(trans + es * 8 + xs) * LOG2E_F;
        const float t_xx = __ldg(trans + xs * 8 + xs) * LOG2E_F;

        const float* emb = em + (size_t)b * T * 8;
        float a_e = (u == 0) ? ((__ldg(bos + es) + __ldg(emb + es)) * LOG2E_F) : NEGF;
        float a_x = NEGF;

        // publish initial boundary (slot 0) + init counters, single barrier
        if (lane == 31) { ring_e[warp][0] = a_e; ring_x[warp][0] = a_x; }
        if (lane == 0)  { cnt[warp] = 0u; }
        __syncthreads();

        // prefetch em for t = 1..4 (clamped), log2-scaled
        float eme0, eme1, eme2, eme3, emx0, emx1, emx2, emx3;
        {
            int t1c = min(1, len - 1), t2c = min(2, len - 1);
            int t3c = min(3, len - 1), t4c = min(4, len - 1);
            eme0 = __ldg(emb + t1c * 8 + es) * LOG2E_F; emx0 = __ldg(emb + t1c * 8 + xs) * LOG2E_F;
            eme1 = __ldg(emb + t2c * 8 + es) * LOG2E_F; emx1 = __ldg(emb + t2c * 8 + xs) * LOG2E_F;
            eme2 = __ldg(emb + t3c * 8 + es) * LOG2E_F; emx2 = __ldg(emb + t3c * 8 + xs) * LOG2E_F;
            eme3 = __ldg(emb + t4c * 8 + es) * LOG2E_F; emx3 = __ldg(emb + t4c * 8 + xs) * LOG2E_F;
        }

        int t = 1;
        for (; t + 3 < len; t += 4) {
            float pe0 = NEGF, px0 = NEGF, pe1 = NEGF, px1 = NEGF;
            float pe2 = NEGF, px2 = NEGF, pe3 = NEGF, px3 = NEGF;
            if (lane == 0) {
                if (warp > 0) {
                    unsigned need = (unsigned)(t + 2);
                    while (ld_acq_shared(&cnt[warp - 1]) < need) { }
                    pe0 = ring_e[warp - 1][(t - 1) & RM]; px0 = ring_x[warp - 1][(t - 1) & RM];
                    pe1 = ring_e[warp - 1][(t    ) & RM]; px1 = ring_x[warp - 1][(t    ) & RM];
                    pe2 = ring_e[warp - 1][(t + 1) & RM]; px2 = ring_x[warp - 1][(t + 1) & RM];
                    pe3 = ring_e[warp - 1][(t + 2) & RM]; px3 = ring_x[warp - 1][(t + 2) & RM];
                }
                // backpressure: never run more than RING-96 ahead of our consumer
                if (warp < 7 && (t & 63) == 1) {
                    int lim = t - (RING - 96);
                    while ((int)ld_acq_shared(&cnt[warp + 1]) < lim) { }
                }
            }
            NUM_STEP(t    , eme0, emx0, pe0, px0);
            NUM_STEP(t + 1, eme1, emx1, pe1, px1);
            NUM_STEP(t + 2, eme2, emx2, pe2, px2);
            NUM_STEP(t + 3, eme3, emx3, pe3, px3);
        }
        // remainder (<=3 steps; len uniform across block)
        if (t < len && lane == 0 && warp > 0) {
            unsigned need = (unsigned)(len - 2);
            while (ld_acq_shared(&cnt[warp - 1]) < need) { }
        }
        if (t < len) {
            float p_e = NEGF, p_x = NEGF;
            if (lane == 0 && warp > 0) { p_e = ring_e[warp-1][(t-1)&RM]; p_x = ring_x[warp-1][(t-1)&RM]; }
            NUM_STEP(t, eme0, emx0, p_e, p_x); t++;
        }
        if (t < len) {
            float p_e = NEGF, p_x = NEGF;
            if (lane == 0 && warp > 0) { p_e = ring_e[warp-1][(t-1)&RM]; p_x = ring_x[warp-1][(t-1)&RM]; }
            NUM_STEP(t, eme1, emx1, p_e, p_x); t++;
        }
        if (t < len) {
            float p_e = NEGF, p_x = NEGF;
            if (lane == 0 && warp > 0) { p_e = ring_e[warp-1][(t-1)&RM]; p_x = ring_x[warp-1][(t-1)&RM]; }
            NUM_STEP(t, eme2, emx2, p_e, p_x); t++;
        }

        const int tl = tlens[b];
        if (u == tl - 1) {
            float fe = a_e + __ldg(eos + es) * LOG2E_F;
            float fx = a_x + __ldg(eos + xs) * LOG2E_F;
            g_num[b] = lae2(fe, fx) * LN2_F;   // back to natural log
        }
    } else {
        // ------------- Denominator Phase A: chunked 8x8 linear-space scan -------------
        const int db = blockIdx.x - B;          // batch
        if (db >= B) return;
        const int c = threadIdx.x >> 3;         // chunk 0..31
        const int i = threadIdx.x & 7;          // row of chunk matrix
        const int len = lengths[db];
        const int C = (T - 1 + NCH - 1) / NCH;  // steps per chunk

        float E[64];
        #pragma unroll
        for (int k = 0; k < 64; ++k) E[k] = __expf(__ldg(trans + k));

        float r[8];
        #pragma unroll
        for (int j = 0; j < 8; ++j) r[j] = (j == i) ? 1.0f : 0.0f;
        float off = 0.0f;

        const int t0 = 1 + c * C;
        const int t1 = min(t0 + C, len);
        const float* emb = em + (size_t)db * T * 8;

        for (int t = t0; t < t1; ++t) {
            float4 lo = __ldg((const float4*)(emb + t * 8));
            float4 hi = __ldg((const float4*)(emb + t * 8 + 4));
            float Em[8];
            Em[0] = __expf(lo.x); Em[1] = __expf(lo.y);
            Em[2] = __expf(lo.z); Em[3] = __expf(lo.w);
            Em[4] = __expf(hi.x); Em[5] = __expf(hi.y);
            Em[6] = __expf(hi.z); Em[7] = __expf(hi.w);

            float s[8];
            #pragma unroll
            for (int j = 0; j < 8; ++j) {
                float acc = r[0] * E[0 * 8 + j];
                #pragma unroll
                for (int k = 1; k < 8; ++k) acc = fmaf(r[k], E[k * 8 + j], acc);
                s[j] = acc * Em[j];
            }
            #pragma unroll
            for (int j = 0; j < 8; ++j) r[j] = s[j];

            if (((t - t0) & 3) == 3) {
                float m = r[0];
                #pragma unroll
                for (int j = 1; j < 8; ++j) m = fmaxf(m, r[j]);
                float inv = __fdividef(1.0f, m);
                off += __logf(m);
                #pragma unroll
                for (int j = 0; j < 8; ++j) r[j] *= inv;
            }
        }

        #pragma unroll
        for (int j = 0; j < 8; ++j) {
            float lv = (r[j] > 0.0f) ? (__logf(r[j]) + off) : NEGF;
            g_LP[(((db * NCH) + c) * 8 + j) * 8 + i] = lv;
        }
    }
}

// Phase B: fold the NCH chunk matrices per batch. 8 threads per batch, all in
// one warp-group-of-8 (width-8 shfl; no barriers in the fold). Depth-4 prefetch.
extern "C" __global__ void __launch_bounds__(128, 1)
ctccrf_finish(const float* __restrict__ em,
              const float* __restrict__ bos,
              const float* __restrict__ eos,
              float* __restrict__ out,
              int B, int T)
{
    __shared__ float sdiff[MAXB];
    const int tid = threadIdx.x;
    const int b = tid >> 3, j = tid & 7;
    const bool active = (b < B);

    float diff = 0.0f;
    if (active) {
        float alpha = __ldg(bos + j) + __ldg(em + (size_t)b * T * 8 + j);  // natural log

        const float* base = g_LP + (size_t)b * NCH * 64 + j * 8;  // row j of chunk c at base + c*64
        float4 plo[4], phi[4];
        #pragma unroll
        for (int k = 0; k < 4; ++k) {
            plo[k] = __ldg((const float4*)(base + k * 64));
            phi[k] = __ldg((const float4*)(base + k * 64 + 4));
        }

        #pragma unroll 4
        for (int c = 0; c < NCH; ++c) {
            float4 lo = plo[c & 3], hi = phi[c & 3];
            int cn = c + 4;
            if (cn < NCH) {
                plo[c & 3] = __ldg((const float4*)(base + cn * 64));
                phi[c & 3] = __ldg((const float4*)(base + cn * 64 + 4));
            }
            float M[8] = {lo.x, lo.y, lo.z, lo.w, hi.x, hi.y, hi.z, hi.w};
            float v[8], m = -3.0e38f;
            #pragma unroll
            for (int i = 0; i < 8; ++i) {
                float ai = __shfl_sync(0xffffffffu, alpha, i, 8);
                v[i] = ai + M[i];
                m = fmaxf(m, v[i]);
            }
            float s = 0.0f;
            #pragma unroll
            for (int i = 0; i < 8; ++i) s += ex2f_((v[i] - m) * LOG2E_F);
            alpha = m + lg2f_(s) * LN2_F;
        }

        // final LSE over j with eos
        float f = alpha + __ldg(eos + j);
        float m = f;
        #pragma unroll
        for (int d = 4; d >= 1; d >>= 1) m = fmaxf(m, __shfl_xor_sync(0xffffffffu, m, d, 8));
        float s = ex2f_((f - m) * LOG2E_F);
        #pragma unroll
        for (int d = 4; d >= 1; d >>= 1) s += __shfl_xor_sync(0xffffffffu, s, d, 8);
        float den = m + lg2f_(s) * LN2_F;
        diff = den - g_num[b];
    }
    if (active && j == 0) sdiff[b] = diff;
    __syncthreads();
    if (tid == 0) {
        float acc = 0.0f;
        for (int bb = 0; bb < B; ++bb) acc += sdiff[bb];
        out[0] = acc / (float)B;
    }
}

extern "C" void kernel_launch(void* const* d_in, const int* in_sizes, int n_in,
                              void* d_out, int out_size)
{
    const float* em     = (const float*)d_in[0];  // (B,T,8)
    const float* trans  = (const float*)d_in[1];  // (8,8)
    const float* bos    = (const float*)d_in[2];  // (8)
    const float* eos    = (const float*)d_in[3];  // (8)
    const int*   lens   = (const int*)  d_in[4];  // (B)
    const int*   tgts   = (const int*)  d_in[5];  // (B,L)
    const int*   tlens  = (const int*)  d_in[6];  // (B)
    float* out = (float*)d_out;

    const int B = in_sizes[4];                 // 16
    const int T = in_sizes[0] / (B * 8);       // 2048
    const int L = in_sizes[5] / B;             // 256

    // Blocks [0,B): numerator (L threads, warp-skewed pipeline).
    // Blocks [B,2B): denominator phase A (NCH chunks x 8 rows = 256 threads).
    ctccrf_main<<<2 * B, 256>>>(em, trans, bos, eos, lens, tgts, tlens, B, T, L);
    ctccrf_finish<<<1, 128>>>(em, bos, eos, out, B, T);
}

// round 4
// speedup vs baseline: 3.7776x; 3.7776x over previous
#include <cuda_runtime.h>
#include <math.h>

#define NEGF    (-1e30f)
#define MAXB    16
#define NCH     32
#define LOG2E_F 1.4426950408889634f
#define LN2_F   0.6931471805599453f
#define RN      2047          // ring slots per boundary (time 0..2046)

// Scratch (static device arrays; no allocations allowed)
__device__ float    g_num[MAXB];                 // numerator logZ per batch (natural log)
__device__ float    g_LP[MAXB * NCH * 8 * 8];    // [b][c][j][i] log chunk matrices
__device__ unsigned g_done = 0;

// ---------------- helpers ----------------
__device__ __forceinline__ float ex2f_(float x) {
    float r; asm("ex2.approx.ftz.f32 %0, %1;" : "=f"(r) : "f"(x)); return r;
}
__device__ __forceinline__ float lg2f_(float x) {
    float r; asm("lg2.approx.ftz.f32 %0, %1;" : "=f"(r) : "f"(x)); return r;
}
// logaddexp in log2 domain: log2(2^a + 2^b)
__device__ __forceinline__ float lae2(float a, float b) {
    float m = fmaxf(a, b);
    float d = fminf(a, b) - m;            // <= 0
    return m + lg2f_(1.0f + ex2f_(d));
}
// volatile 64-bit shared ld/st (single STS.64 / LDS.64; data word doubles as flag)
__device__ __forceinline__ float2 lds64v(const float2* p) {
    float2 v; unsigned a = (unsigned)__cvta_generic_to_shared(p);
    asm volatile("ld.volatile.shared.v2.f32 {%0,%1},[%2];" : "=f"(v.x), "=f"(v.y) : "r"(a));
    return v;
}
__device__ __forceinline__ void sts64v(float2* p, float2 v) {
    unsigned a = (unsigned)__cvta_generic_to_shared(p);
    asm volatile("st.volatile.shared.v2.f32 [%0],{%1,%2};" :: "r"(a), "f"(v.x), "f"(v.y));
}
__device__ __forceinline__ int isnanf_(float x) { return x != x; }

// One numerator step (log2 domain), thread owns lanes u0=2k (even), u1=2k+1 (odd).
// PE_/PX_ used by lane 0 only (boundary from ring or NEGF for warp 0).
#define NUM_STEP(T_, J_, PE_, PX_) do {                                        \
    float pe_ = __shfl_up_sync(0xffffffffu, a_e1, 1);                          \
    float px_ = __shfl_up_sync(0xffffffffu, a_x1, 1);                          \
    if (lane == 0) { pe_ = (PE_); px_ = (PX_); }                               \
    float ne0_ = eme0[J_] + lae2(pe_  + t_ee0, px_  + t_xe0);                  \
    float nx0_ = emx0[J_] + lae2(a_e0 + t_ex0, a_x0 + t_xx0);                  \
    float ne1_ = eme1[J_] + lae2(a_e0 + t_ee1, a_x0 + t_xe1);                  \
    float nx1_ = emx1[J_] + lae2(a_e1 + t_ex1, a_x1 + t_xx1);                  \
    int tp_ = min((T_) + 4, len - 1);                                          \
    eme0[J_] = __ldg(emb + tp_ * 8 + es0) * LOG2E_F;                           \
    emx0[J_] = __ldg(emb + tp_ * 8 + xs0) * LOG2E_F;                           \
    eme1[J_] = __ldg(emb + tp_ * 8 + es1) * LOG2E_F;                           \
    emx1[J_] = __ldg(emb + tp_ * 8 + xs1) * LOG2E_F;                           \
    a_e0 = ne0_; a_x0 = nx0_; a_e1 = ne1_; a_x1 = nx1_;                        \
    if (lane == 31 && warp < 3 && (T_) <= len - 2)                             \
        sts64v(&rprod[(T_)], make_float2(a_e1, a_x1));                         \
} while (0)

extern "C" __global__ void __launch_bounds__(256, 1)
ctccrf_fused(const float* __restrict__ em,      // (B,T,8)
             const float* __restrict__ trans,   // (8,8)
             const float* __restrict__ bos,     // (8)
             const float* __restrict__ eos,     // (8)
             const int*   __restrict__ lengths, // (B)
             const int*   __restrict__ targets, // (B,L)
             const int*   __restrict__ tlens,   // (B)
             float* __restrict__ out,
             int B, int T, int L)
{
    __shared__ float2 s_ring[3][RN];   // 49,128 B
    __shared__ int    s_flag;
    const int tid = threadIdx.x;

    if ((int)blockIdx.x < B) {
        // ---------------- Numerator: 128 workers, 2 lanes/thread, skewed warps ----------------
        const float NANSENT = __int_as_float(0x7fc00000);
        for (int i = tid; i < 3 * RN; i += 256)
            ((float2*)s_ring)[i] = make_float2(NANSENT, NANSENT);
        __syncthreads();

        if (tid < (L >> 1)) {
            const int b    = blockIdx.x;
            const int k    = tid;
            const int lane = k & 31;
            const int warp = k >> 5;
            const int u0 = 2 * k, u1 = 2 * k + 1;

            const int len = lengths[b];
            const int lenm2 = len - 2;
            const int tg0 = __ldg(targets + b * L + u0);
            const int tg1 = __ldg(targets + b * L + u1);
            const int es0 = tg0, xs0 = tg0 + 4;
            const int es1 = tg1, xs1 = tg1 + 4;
            const int tgp0 = (u0 == 0) ? tg0 : __ldg(targets + b * L + u0 - 1);

            const float t_ee0 = __ldg(trans + tgp0 * 8 + es0) * LOG2E_F;
            const float t_xe0 = __ldg(trans + (tgp0 + 4) * 8 + es0) * LOG2E_F;
            const float t_ex0 = __ldg(trans + es0 * 8 + xs0) * LOG2E_F;
            const float t_xx0 = __ldg(trans + xs0 * 8 + xs0) * LOG2E_F;
            const float t_ee1 = __ldg(trans + tg0 * 8 + es1) * LOG2E_F;       // prev of u1 is u0
            const float t_xe1 = __ldg(trans + (tg0 + 4) * 8 + es1) * LOG2E_F;
            const float t_ex1 = __ldg(trans + es1 * 8 + xs1) * LOG2E_F;
            const float t_xx1 = __ldg(trans + xs1 * 8 + xs1) * LOG2E_F;

            const float* emb = em + (size_t)b * T * 8;
            float a_e0 = (u0 == 0) ? ((__ldg(bos + es0) + __ldg(emb + es0)) * LOG2E_F) : NEGF;
            float a_x0 = NEGF, a_e1 = NEGF, a_x1 = NEGF;

            float2*       rprod = s_ring[(warp < 3) ? warp : 0];
            const float2* rcons = s_ring[(warp > 0) ? (warp - 1) : 0];

            // publish initial boundary (time 0); consumers synchronize via sentinel polling
            if (lane == 31 && warp < 3) sts64v(&rprod[0], make_float2(a_e1, a_x1));

            // em prefetch for steps 1..4 (clamped), log2-scaled
            float eme0[4], emx0[4], eme1[4], emx1[4];
            #pragma unroll
            for (int j = 0; j < 4; ++j) {
                int tc = min(1 + j, len - 1);
                eme0[j] = __ldg(emb + tc * 8 + es0) * LOG2E_F;
                emx0[j] = __ldg(emb + tc * 8 + xs0) * LOG2E_F;
                eme1[j] = __ldg(emb + tc * 8 + es1) * LOG2E_F;
                emx1[j] = __ldg(emb + tc * 8 + xs1) * LOG2E_F;
            }

            float2 cur0 = make_float2(NEGF, NEGF), cur1 = cur0, cur2 = cur0, cur3 = cur0;
            float2 nxt0 = cur0, nxt1 = cur0, nxt2 = cur0, nxt3 = cur0;
            if (lane == 0 && warp > 0) {
                cur0 = lds64v(&rcons[0]);
                cur1 = lds64v(&rcons[min(1, lenm2)]);
                cur2 = lds64v(&rcons[min(2, lenm2)]);
                cur3 = lds64v(&rcons[min(3, lenm2)]);
            }

            int t = 1;
            for (; t + 3 < len; t += 4) {
                if (lane == 0 && warp > 0) {
                    // validate prefetched boundaries (rare retry at startup ramp)
                    while (isnanf_(cur0.x) | isnanf_(cur1.x) | isnanf_(cur2.x) | isnanf_(cur3.x)) {
                        cur0 = lds64v(&rcons[t - 1]);
                        cur1 = lds64v(&rcons[t]);
                        cur2 = lds64v(&rcons[t + 1]);
                        cur3 = lds64v(&rcons[t + 2]);
                    }
                    // prefetch next group's boundaries (slots t+3..t+6, clamped)
                    nxt0 = lds64v(&rcons[min(t + 3, lenm2)]);
                    nxt1 = lds64v(&rcons[min(t + 4, lenm2)]);
                    nxt2 = lds64v(&rcons[min(t + 5, lenm2)]);
                    nxt3 = lds64v(&rcons[min(t + 6, lenm2)]);
                }
                NUM_STEP(t,     0, cur0.x, cur0.y);
                NUM_STEP(t + 1, 1, cur1.x, cur1.y);
                NUM_STEP(t + 2, 2, cur2.x, cur2.y);
                NUM_STEP(t + 3, 3, cur3.x, cur3.y);
                cur0 = nxt0; cur1 = nxt1; cur2 = nxt2; cur3 = nxt3;
            }
            // tail (<=3 steps; len uniform across block)
            if (t < len) {
                float2 bb = make_float2(NEGF, NEGF);
                if (lane == 0 && warp > 0) { do { bb = lds64v(&rcons[t - 1]); } while (isnanf_(bb.x)); }
                NUM_STEP(t, 0, bb.x, bb.y); t++;
            }
            if (t < len) {
                float2 bb = make_float2(NEGF, NEGF);
                if (lane == 0 && warp > 0) { do { bb = lds64v(&rcons[t - 1]); } while (isnanf_(bb.x)); }
                NUM_STEP(t, 1, bb.x, bb.y); t++;
            }
            if (t < len) {
                float2 bb = make_float2(NEGF, NEGF);
                if (lane == 0 && warp > 0) { do { bb = lds64v(&rcons[t - 1]); } while (isnanf_(bb.x)); }
                NUM_STEP(t, 2, bb.x, bb.y); t++;
            }

            const int tl = __ldg(tlens + b);
            if (u0 == tl - 1)
                g_num[b] = lae2(a_e0 + __ldg(eos + es0) * LOG2E_F,
                                a_x0 + __ldg(eos + xs0) * LOG2E_F) * LN2_F;
            if (u1 == tl - 1)
                g_num[b] = lae2(a_e1 + __ldg(eos + es1) * LOG2E_F,
                                a_x1 + __ldg(eos + xs1) * LOG2E_F) * LN2_F;
        }
    } else {
        // ------------- Denominator Phase A: chunked 8x8 linear-space scan -------------
        const int db = blockIdx.x - B;          // batch (grid is exactly 2B)
        const int c = tid >> 3;                 // chunk 0..31
        const int i = tid & 7;                  // row of chunk matrix
        const int len = lengths[db];
        const int C = (T - 1 + NCH - 1) / NCH;

        float E[64];
        #pragma unroll
        for (int k = 0; k < 64; ++k) E[k] = __expf(__ldg(trans + k));

        float r[8];
        #pragma unroll
        for (int j = 0; j < 8; ++j) r[j] = (j == i) ? 1.0f : 0.0f;
        float off = 0.0f;

        const int t0 = 1 + c * C;
        const int t1 = min(t0 + C, len);
        const float* emb = em + (size_t)db * T * 8;

        for (int t = t0; t < t1; ++t) {
            float4 lo = __ldg((const float4*)(emb + t * 8));
            float4 hi = __ldg((const float4*)(emb + t * 8 + 4));
            float Em[8];
            Em[0] = __expf(lo.x); Em[1] = __expf(lo.y);
            Em[2] = __expf(lo.z); Em[3] = __expf(lo.w);
            Em[4] = __expf(hi.x); Em[5] = __expf(hi.y);
            Em[6] = __expf(hi.z); Em[7] = __expf(hi.w);

            float s[8];
            #pragma unroll
            for (int j = 0; j < 8; ++j) {
                float acc = r[0] * E[0 * 8 + j];
                #pragma unroll
                for (int kk = 1; kk < 8; ++kk) acc = fmaf(r[kk], E[kk * 8 + j], acc);
                s[j] = acc * Em[j];
            }
            #pragma unroll
            for (int j = 0; j < 8; ++j) r[j] = s[j];

            if (((t - t0) & 3) == 3) {
                float m = r[0];
                #pragma unroll
                for (int j = 1; j < 8; ++j) m = fmaxf(m, r[j]);
                float inv = __fdividef(1.0f, m);
                off += __logf(m);
                #pragma unroll
                for (int j = 0; j < 8; ++j) r[j] *= inv;
            }
        }

        #pragma unroll
        for (int j = 0; j < 8; ++j) {
            float lv = (r[j] > 0.0f) ? (__logf(r[j]) + off) : NEGF;
            g_LP[(((db * NCH) + c) * 8 + j) * 8 + i] = lv;
        }
    }

    // ---------------- Fused finish: last block folds chunks + reduces ----------------
    __threadfence();
    __syncthreads();
    if (tid == 0) {
        unsigned old = atomicAdd(&g_done, 1u);
        s_flag = (old == (unsigned)(2 * B - 1));
    }
    __syncthreads();
    if (s_flag) {
        __threadfence();
        float* sdiff = (float*)s_ring;          // ring no longer needed
        const int  bq = min(tid >> 3, B - 1);   // clamp so all 256 threads run shfls
        const int  j  = tid & 7;
        const bool active = (tid >> 3) < B;

        float alpha = __ldg(bos + j) + __ldg(em + (size_t)bq * T * 8 + j);  // natural log
        const float* base = g_LP + (size_t)bq * NCH * 64 + j * 8;
        float4 plo[4], phi[4];
        #pragma unroll
        for (int kk = 0; kk < 4; ++kk) {
            plo[kk] = __ldg((const float4*)(base + kk * 64));
            phi[kk] = __ldg((const float4*)(base + kk * 64 + 4));
        }
        #pragma unroll 4
        for (int c = 0; c < NCH; ++c) {
            float4 lo = plo[c & 3], hi = phi[c & 3];
            int cn = c + 4;
            if (cn < NCH) {
                plo[c & 3] = __ldg((const float4*)(base + cn * 64));
                phi[c & 3] = __ldg((const float4*)(base + cn * 64 + 4));
            }
            float M[8] = {lo.x, lo.y, lo.z, lo.w, hi.x, hi.y, hi.z, hi.w};
            float v[8], m = -3.0e38f;
            #pragma unroll
            for (int i2 = 0; i2 < 8; ++i2) {
                float ai = __shfl_sync(0xffffffffu, alpha, i2, 8);
                v[i2] = ai + M[i2];
                m = fmaxf(m, v[i2]);
            }
            float s = 0.0f;
            #pragma unroll
            for (int i2 = 0; i2 < 8; ++i2) s += ex2f_((v[i2] - m) * LOG2E_F);
            alpha = m + lg2f_(s) * LN2_F;
        }
        float f = alpha + __ldg(eos + j);
        float m = f;
        #pragma unroll
        for (int d = 4; d >= 1; d >>= 1) m = fmaxf(m, __shfl_xor_sync(0xffffffffu, m, d, 8));
        float s = ex2f_((f - m) * LOG2E_F);
        #pragma unroll
        for (int d = 4; d >= 1; d >>= 1) s += __shfl_xor_sync(0xffffffffu, s, d, 8);
        float den = m + lg2f_(s) * LN2_F;

        if (active && j == 0) sdiff[tid >> 3] = den - g_num[bq];
        __syncthreads();
        if (tid == 0) {
            float acc = 0.0f;
            for (int bb = 0; bb < B; ++bb) acc += sdiff[bb];
            out[0] = acc / (float)B;
            g_done = 0;                         // reset for next graph replay
        }
    }
}

extern "C" void kernel_launch(void* const* d_in, const int* in_sizes, int n_in,
                              void* d_out, int out_size)
{
    const float* em     = (const float*)d_in[0];  // (B,T,8)
    const float* trans  = (const float*)d_in[1];  // (8,8)
    const float* bos    = (const float*)d_in[2];  // (8)
    const float* eos    = (const float*)d_in[3];  // (8)
    const int*   lens   = (const int*)  d_in[4];  // (B)
    const int*   tgts   = (const int*)  d_in[5];  // (B,L)
    const int*   tlens  = (const int*)  d_in[6];  // (B)
    float* out = (float*)d_out;

    const int B = in_sizes[4];                 // 16
    const int T = in_sizes[0] / (B * 8);       // 2048
    const int L = in_sizes[5] / B;             // 256

    // Blocks [0,B): numerator (L/2 workers, sentinel-ring skewed warps).
    // Blocks [B,2B): denominator phase A. Last-done block runs the finish fold.
    ctccrf_fused<<<2 * B, 256>>>(em, trans, bos, eos, lens, tgts, tlens, out, B, T, L);
}